// round 8
// baseline (speedup 1.0000x reference)
#include <cuda_runtime.h>
#include <cuda_bf16.h>
#include <cstdint>
#include <math.h>

// ---------------- device scratch (allocation-free) ----------------
__device__ __align__(16) __nv_bfloat16 g_xhi[256 * 1024];
__device__ __align__(16) __nv_bfloat16 g_xlo[256 * 1024];
__device__ __align__(16) __nv_bfloat16 g_Whi[512 * 1024];
__device__ __align__(16) __nv_bfloat16 g_Wlo[512 * 1024];
__device__ __align__(16) __nv_bfloat16 g_ub [512 * 1024];   // bf16(expm1(u[k][n])), [k][n]
__device__ __align__(16) __nv_bfloat16 g_Ebf[256 * 512];    // bf16(E)
__device__ float g_rs[16 * 256];                            // per-(ntile,row) rowsums of E

// ---------------- helpers ----------------
__device__ __forceinline__ uint32_t smem_u32(const void* p) {
    uint32_t a;
    asm("{ .reg .u64 t; cvta.to.shared.u64 t, %1; cvt.u32.u64 %0, t; }" : "=r"(a) : "l"(p));
    return a;
}
__device__ __forceinline__ void cp16(uint32_t dst, const void* src) {
    asm volatile("cp.async.cg.shared.global [%0], [%1], 16;" :: "r"(dst), "l"(src) : "memory");
}
#define CP_COMMIT() asm volatile("cp.async.commit_group;" ::: "memory")
#define CP_WAIT2()  asm volatile("cp.async.wait_group 2;" ::: "memory")
#define CP_WAIT1()  asm volatile("cp.async.wait_group 1;" ::: "memory")
#define CP_WAIT0()  asm volatile("cp.async.wait_group 0;" ::: "memory")
// tail-correct wait: stage c must be complete; groups are committed one per chunk
#define CP_WAIT_FOR(c, C) do { \
    if ((c) < (C) - 2) { CP_WAIT2(); } \
    else if ((c) == (C) - 2) { CP_WAIT1(); } \
    else { CP_WAIT0(); } \
} while (0)

__device__ __forceinline__ void ldsm4(uint32_t* r, uint32_t addr) {
    asm volatile("ldmatrix.sync.aligned.m8n8.x4.shared.b16 {%0,%1,%2,%3}, [%4];"
        : "=r"(r[0]), "=r"(r[1]), "=r"(r[2]), "=r"(r[3]) : "r"(addr));
}
__device__ __forceinline__ void ldsm4t(uint32_t* r, uint32_t addr) {
    asm volatile("ldmatrix.sync.aligned.m8n8.x4.trans.shared.b16 {%0,%1,%2,%3}, [%4];"
        : "=r"(r[0]), "=r"(r[1]), "=r"(r[2]), "=r"(r[3]) : "r"(addr));
}
__device__ __forceinline__ void mma_bf16(float* c, const uint32_t* a, uint32_t b0, uint32_t b1) {
    asm volatile("mma.sync.aligned.m16n8k16.row.col.f32.bf16.bf16.f32 "
        "{%0,%1,%2,%3}, {%4,%5,%6,%7}, {%8,%9}, {%0,%1,%2,%3};"
        : "+f"(c[0]), "+f"(c[1]), "+f"(c[2]), "+f"(c[3])
        : "r"(a[0]), "r"(a[1]), "r"(a[2]), "r"(a[3]), "r"(b0), "r"(b1));
}

__device__ __forceinline__ void split4(float4 v, uint2& hi, uint2& lo) {
    __nv_bfloat16 h0 = __float2bfloat16(v.x), h1 = __float2bfloat16(v.y);
    __nv_bfloat16 h2 = __float2bfloat16(v.z), h3 = __float2bfloat16(v.w);
    __nv_bfloat162 hp0{h0, h1}, hp1{h2, h3};
    __nv_bfloat162 lp0{__float2bfloat16(v.x - __bfloat162float(h0)),
                       __float2bfloat16(v.y - __bfloat162float(h1))};
    __nv_bfloat162 lp1{__float2bfloat16(v.z - __bfloat162float(h2)),
                       __float2bfloat16(v.w - __bfloat162float(h3))};
    hi = make_uint2(*(uint32_t*)&hp0, *(uint32_t*)&hp1);
    lo = make_uint2(*(uint32_t*)&lp0, *(uint32_t*)&lp1);
}

// expm1 for u in [0,1e-3]: 3 FFMA, no MUFU
__device__ __forceinline__ float expm1_small(float u) {
    return u * fmaf(u, fmaf(u, 0.16666667f, 0.5f), 1.0f);
}
__device__ __forceinline__ uint32_t poly_pack2(float a, float b) {
    __nv_bfloat162 v = __floats2bfloat162_rn(expm1_small(a), expm1_small(b));
    return *(uint32_t*)&v;
}

// ============================================================
// prep: bf16 hi/lo splits of x and W only. 384 blocks x 256 thr, 2 f4/thread.
// ============================================================
__global__ __launch_bounds__(256) void prep_kernel(
    const float* __restrict__ x, const float* __restrict__ W)
{
    const int b = blockIdx.x, t = threadIdx.x;
    const float4* src;
    __nv_bfloat16 *dhi, *dlo;
    int base;  // float4 units; each block covers 512 f4
    if (b < 128) { src = (const float4*)x; dhi = g_xhi; dlo = g_xlo; base = b * 512; }
    else         { src = (const float4*)W; dhi = g_Whi; dlo = g_Wlo; base = (b - 128) * 512; }
    float4 v0 = src[base + t];
    float4 v1 = src[base + 256 + t];
    uint2 hi, lo;
    split4(v0, hi, lo);
    *(uint2*)&dhi[(base + t) * 4] = hi;
    *(uint2*)&dlo[(base + t) * 4] = lo;
    split4(v1, hi, lo);
    *(uint2*)&dhi[(base + 256 + t) * 4] = hi;
    *(uint2*)&dlo[(base + 256 + t) * 4] = lo;
}

// ============================================================
// GEMM1: E = exp(x @ W^T), bf16x3, 4-stage cp.async, chunks of K=128
// tile 32Mx32N, grid 128 (16nt x 8mt), 512 thr / 16 warps (2x2 space, 4-way k)
// ALSO converts u -> g_ub (each CTA does 1/128 of u, hidden under pipeline fill)
// ============================================================
constexpr int P1    = 136;               // bf16 row pitch (272B)
constexpr int T1E   = 32 * P1;           // tile elems
constexpr int STG1E = 4 * T1E;           // Ahi|Alo|Bhi|Blo
constexpr int G1_DSMEM = 4 * STG1E * 2;  // 139264 B

__global__ __launch_bounds__(512) void gemm1_kernel(const float* __restrict__ u)
{
    extern __shared__ __nv_bfloat16 sm[];
    __shared__ float sred[12][32][8];
    __shared__ float srs[2][32];

    const int tid = threadIdx.x, lane = tid & 31, wid = tid >> 5;
    const int nt = blockIdx.x & 15;
    const int m0 = (blockIdx.x >> 4) * 32, n0 = nt * 32;
    const uint32_t sb = smem_u32(sm);

    // ---- u rider: issue LDG first so latency hides under pipeline fill ----
    const int ubase = blockIdx.x * 1024 + tid * 2;     // float4 index
    float4 uv0 = ((const float4*)u)[ubase];
    float4 uv1 = ((const float4*)u)[ubase + 1];

    // ---- loader mapping: 4 tiles x 128 thr; thread = 1 row x 4 cp16 (64B) ----
    const int tileid = tid >> 7, local = tid & 127;
    const int rowL = local >> 2, colq = (local & 3) * 32;     // elems
    const __nv_bfloat16* gsrc =
        (tileid == 0 ? g_xhi + m0 * 1024 :
         tileid == 1 ? g_xlo + m0 * 1024 :
         tileid == 2 ? g_Whi + n0 * 1024 : g_Wlo + n0 * 1024)
        + rowL * 1024 + colq;
    const uint32_t sdst = sb + (uint32_t)((tileid * T1E + rowL * P1 + colq) * 2);

    #define G1_ISSUE(c) do { \
        const uint32_t _d = sdst + ((c) & 3) * (STG1E * 2); \
        const __nv_bfloat16* _s = gsrc + (c) * 128; \
        cp16(_d,      _s);      cp16(_d + 16, _s + 8); \
        cp16(_d + 32, _s + 16); cp16(_d + 48, _s + 24); \
        CP_COMMIT(); \
    } while (0)

    G1_ISSUE(0); G1_ISSUE(1); G1_ISSUE(2);

    // ---- u rider: convert + store (overlaps with cp.async fill) ----
    *(uint2*)&g_ub[ubase * 4]     = make_uint2(poly_pack2(uv0.x, uv0.y), poly_pack2(uv0.z, uv0.w));
    *(uint2*)&g_ub[ubase * 4 + 4] = make_uint2(poly_pack2(uv1.x, uv1.y), poly_pack2(uv1.z, uv1.w));

    // ---- compute mapping ----
    const int wn = wid & 1, wm = (wid >> 1) & 1, wk = wid >> 2;   // wk: 0..3
    const int lrow = lane & 15;
    const int lk = (lane >> 4) << 3;
    const uint32_t aOff = (uint32_t)(((wm * 16 + lrow) * P1 + lk) * 2);
    const uint32_t bOff = (uint32_t)(((wn * 16 + lrow) * P1 + lk) * 2);

    float hh0[4] = {}, hh1[4] = {}, hl0[4] = {}, hl1[4] = {}, lh0[4] = {}, lh1[4] = {};

    const int C = 8;
    for (int c = 0; c < C; c++) {
        CP_WAIT_FOR(c, C);
        __syncthreads();
        if (c + 3 < C) G1_ISSUE(c + 3);
        const uint32_t st = sb + (c & 3) * (STG1E * 2);
        #pragma unroll
        for (int j = 0; j < 2; j++) {
            const int ks = wk * 2 + j;           // 0..7 ksteps of 16
            uint32_t a_hi[4], a_lo[4], b_hi[4], b_lo[4];
            ldsm4(a_hi, st + aOff + ks * 32);
            ldsm4(a_lo, st + T1E * 2 + aOff + ks * 32);
            ldsm4(b_hi, st + 2 * T1E * 2 + bOff + ks * 32);
            ldsm4(b_lo, st + 3 * T1E * 2 + bOff + ks * 32);
            mma_bf16(hh0, a_hi, b_hi[0], b_hi[2]);
            mma_bf16(hh1, a_hi, b_hi[1], b_hi[3]);
            mma_bf16(hl0, a_hi, b_lo[0], b_lo[2]);
            mma_bf16(hl1, a_hi, b_lo[1], b_lo[3]);
            mma_bf16(lh0, a_lo, b_hi[0], b_hi[2]);
            mma_bf16(lh1, a_lo, b_hi[1], b_hi[3]);
        }
    }
    #undef G1_ISSUE

    float acc0[4], acc1[4];
    #pragma unroll
    for (int i = 0; i < 4; i++) {
        acc0[i] = hh0[i] + hl0[i] + lh0[i];
        acc1[i] = hh1[i] + hl1[i] + lh1[i];
    }

    // ---- 4-way k-split reduction ----
    if (wk != 0) {
        #pragma unroll
        for (int i = 0; i < 4; i++) {
            sred[(wk - 1) * 4 + (wid & 3)][lane][i]     = acc0[i];
            sred[(wk - 1) * 4 + (wid & 3)][lane][4 + i] = acc1[i];
        }
    }
    __syncthreads();

    if (wk == 0) {
        #pragma unroll
        for (int q = 0; q < 3; q++)
            #pragma unroll
            for (int i = 0; i < 4; i++) {
                acc0[i] += sred[q * 4 + wid][lane][i];
                acc1[i] += sred[q * 4 + wid][lane][4 + i];
            }
        // ---- epilogue: exp, bf16 E, fp32 rowsum ----
        const int qr = lane >> 2;
        const int qc = (lane & 3) * 2;
        const int mrow0 = m0 + wm * 16 + qr;
        const int mrow1 = mrow0 + 8;
        float p0 = 0.f, p1 = 0.f;
        #pragma unroll
        for (int g = 0; g < 2; g++) {
            float* acc = g ? acc1 : acc0;
            float e0 = expf(acc[0]), e1 = expf(acc[1]);
            float e2 = expf(acc[2]), e3 = expf(acc[3]);
            p0 += e0 + e1; p1 += e2 + e3;
            const int n = n0 + wn * 16 + g * 8 + qc;
            __nv_bfloat162 v0 = __floats2bfloat162_rn(e0, e1);
            __nv_bfloat162 v1 = __floats2bfloat162_rn(e2, e3);
            *(uint32_t*)&g_Ebf[mrow0 * 512 + n] = *(uint32_t*)&v0;
            *(uint32_t*)&g_Ebf[mrow1 * 512 + n] = *(uint32_t*)&v1;
        }
        p0 += __shfl_xor_sync(0xFFFFFFFFu, p0, 1);
        p0 += __shfl_xor_sync(0xFFFFFFFFu, p0, 2);
        p1 += __shfl_xor_sync(0xFFFFFFFFu, p1, 1);
        p1 += __shfl_xor_sync(0xFFFFFFFFu, p1, 2);
        if ((lane & 3) == 0) {
            srs[wn][wm * 16 + qr]     = p0;
            srs[wn][wm * 16 + qr + 8] = p1;
        }
    }
    __syncthreads();
    if (tid < 32) g_rs[nt * 256 + m0 + tid] = srs[0][tid] + srs[1][tid];
}

// ============================================================
// GEMM2: y = E_bf16 @ g_ub + rowsum(E) + 512
// tile 32Mx64N, grid 128 (16nt x 8mt), 512 thr / 16 warps, chunks of K=128 (4)
// B via ldmatrix.trans on [k][n] u tiles; 4-stage cp.async
// ============================================================
constexpr int P2    = 136;
constexpr int ET2E  = 32 * P2;            // E tile elems
constexpr int UT2E  = 128 * P2;           // u tile elems (128 krows x 64 n, padded)
constexpr int STG2E = ET2E + UT2E;
constexpr int G2_DSMEM = 4 * STG2E * 2;   // 174080 B

__global__ __launch_bounds__(512) void gemm2_kernel(float* __restrict__ Y)
{
    extern __shared__ __nv_bfloat16 sm[];
    __shared__ float sred[12][32][16];
    __shared__ float rst[32];

    const int tid = threadIdx.x, lane = tid & 31, wid = tid >> 5;
    const int n0 = (blockIdx.x & 15) * 64;
    const int m0 = (blockIdx.x >> 4) * 32;
    const uint32_t sb = smem_u32(sm);

    if (tid < 32) {
        float s = 512.0f;
        #pragma unroll
        for (int j = 0; j < 16; j++) s += g_rs[j * 256 + m0 + tid];
        rst[tid] = s;
    }

    // ---- loader: E 512 cp16 (1/thread), u 1024 cp16 (2/thread) per chunk ----
    const int rowE = tid >> 4, segE = tid & 15;
    const __nv_bfloat16* aSrc = g_Ebf + (m0 + rowE) * 512 + segE * 8;
    const uint32_t aDst = sb + (uint32_t)((rowE * P2 + segE * 8) * 2);
    const int uIdx0 = tid * 2, uIdx1 = tid * 2 + 1;
    const int kr0 = uIdx0 >> 3, sg0 = uIdx0 & 7;
    const int kr1 = uIdx1 >> 3, sg1 = uIdx1 & 7;
    const __nv_bfloat16* bSrc0 = g_ub + kr0 * 1024 + n0 + sg0 * 8;
    const __nv_bfloat16* bSrc1 = g_ub + kr1 * 1024 + n0 + sg1 * 8;
    const uint32_t bDst0 = sb + (uint32_t)((ET2E + kr0 * P2 + sg0 * 8) * 2);
    const uint32_t bDst1 = sb + (uint32_t)((ET2E + kr1 * P2 + sg1 * 8) * 2);

    #define G2_ISSUE(c) do { \
        const uint32_t _so = ((c) & 3) * (STG2E * 2); \
        cp16(aDst + _so, aSrc + (c) * 128); \
        cp16(bDst0 + _so, bSrc0 + (c) * 128 * 1024); \
        cp16(bDst1 + _so, bSrc1 + (c) * 128 * 1024); \
        CP_COMMIT(); \
    } while (0)

    // ---- compute mapping ----
    const int wn = wid & 1, wm = (wid >> 1) & 1, wk = wid >> 2;
    const int lrow = lane & 15;
    const int lk = (lane >> 4) << 3;
    const uint32_t aOff = (uint32_t)(((wm * 16 + lrow) * P2 + lk) * 2);
    const int li = lane & 7, kbit = (lane >> 3) & 1, nq = lane >> 4;
    const uint32_t tOff = (uint32_t)((((kbit * 8 + li) * P2) + nq * 8) * 2);

    float acc[4][4] = {};

    G2_ISSUE(0); G2_ISSUE(1); G2_ISSUE(2);

    const int C = 4;
    for (int c = 0; c < C; c++) {
        CP_WAIT_FOR(c, C);
        __syncthreads();
        if (c + 3 < C) G2_ISSUE(c + 3);
        const uint32_t st = sb + (c & 3) * (STG2E * 2);
        const uint32_t stU = st + ET2E * 2;
        #pragma unroll
        for (int j = 0; j < 2; j++) {
            const int ks = wk * 2 + j;           // 0..7
            uint32_t a[4], bq0[4], bq1[4];
            ldsm4(a, st + aOff + ks * 32);
            ldsm4t(bq0, stU + tOff + ks * 16 * P2 * 2 + (wn * 32 + 0) * 2);
            ldsm4t(bq1, stU + tOff + ks * 16 * P2 * 2 + (wn * 32 + 16) * 2);
            mma_bf16(acc[0], a, bq0[0], bq0[1]);
            mma_bf16(acc[1], a, bq0[2], bq0[3]);
            mma_bf16(acc[2], a, bq1[0], bq1[1]);
            mma_bf16(acc[3], a, bq1[2], bq1[3]);
        }
    }
    #undef G2_ISSUE

    if (wk != 0) {
        #pragma unroll
        for (int g = 0; g < 4; g++)
            #pragma unroll
            for (int i = 0; i < 4; i++)
                sred[(wk - 1) * 4 + (wid & 3)][lane][g * 4 + i] = acc[g][i];
    }
    __syncthreads();

    if (wk == 0) {
        #pragma unroll
        for (int q = 0; q < 3; q++)
            #pragma unroll
            for (int g = 0; g < 4; g++)
                #pragma unroll
                for (int i = 0; i < 4; i++)
                    acc[g][i] += sred[q * 4 + wid][lane][g * 4 + i];

        const int qr = lane >> 2;
        const int qc = (lane & 3) * 2;
        const int mrow0 = m0 + wm * 16 + qr;
        const int mrow1 = mrow0 + 8;
        const float r0v = rst[wm * 16 + qr];
        const float r1v = rst[wm * 16 + qr + 8];
        #pragma unroll
        for (int g = 0; g < 4; g++) {
            const int n = n0 + wn * 32 + g * 8 + qc;
            *(float2*)(Y + mrow0 * 1024 + n) = make_float2(acc[g][0] + r0v, acc[g][1] + r0v);
            *(float2*)(Y + mrow1 * 1024 + n) = make_float2(acc[g][2] + r1v, acc[g][3] + r1v);
        }
    }
}

// ============================================================
extern "C" void kernel_launch(void* const* d_in, const int* in_sizes, int n_in,
                              void* d_out, int out_size)
{
    const float* x = (const float*)d_in[0];   // 256 x 1024
    const float* W = (const float*)d_in[1];   // 512 x 1024
    const float* u = (const float*)d_in[2];   // 512 x 1024
    float* y = (float*)d_out;                 // 256 x 1024

    cudaFuncSetAttribute(gemm1_kernel, cudaFuncAttributeMaxDynamicSharedMemorySize, G1_DSMEM);
    cudaFuncSetAttribute(gemm2_kernel, cudaFuncAttributeMaxDynamicSharedMemorySize, G2_DSMEM);

    prep_kernel<<<384, 256>>>(x, W);
    gemm1_kernel<<<128, 512, G1_DSMEM>>>(u);
    gemm2_kernel<<<128, 512, G2_DSMEM>>>(y);
}

// round 9
// speedup vs baseline: 1.0062x; 1.0062x over previous
#include <cuda_runtime.h>
#include <cuda_bf16.h>
#include <cstdint>
#include <math.h>

// ---------------- device scratch (allocation-free) ----------------
__device__ __align__(16) __nv_bfloat16 g_ub [512 * 1024];   // bf16(expm1(u[k][n])), [k][n]
__device__ __align__(16) __nv_bfloat16 g_Ebf[256 * 512];    // bf16(E)
__device__ float g_rs[16 * 256];                            // per-(ntile,row) rowsums of E
__device__ unsigned g_count = 0;                            // grid-sync arrivals
__device__ unsigned g_epoch = 0;                            // grid-sync epoch (monotonic)

// ---------------- helpers ----------------
__device__ __forceinline__ uint32_t smem_u32(const void* p) {
    uint32_t a;
    asm("{ .reg .u64 t; cvta.to.shared.u64 t, %1; cvt.u32.u64 %0, t; }" : "=r"(a) : "l"(p));
    return a;
}
__device__ __forceinline__ void cp16(uint32_t dst, const void* src) {
    asm volatile("cp.async.cg.shared.global [%0], [%1], 16;" :: "r"(dst), "l"(src) : "memory");
}
#define CP_COMMIT() asm volatile("cp.async.commit_group;" ::: "memory")
#define CP_WAITN(n) asm volatile("cp.async.wait_group %0;" :: "n"(n) : "memory")

__device__ __forceinline__ void ldsm4(uint32_t* r, uint32_t addr) {
    asm volatile("ldmatrix.sync.aligned.m8n8.x4.shared.b16 {%0,%1,%2,%3}, [%4];"
        : "=r"(r[0]), "=r"(r[1]), "=r"(r[2]), "=r"(r[3]) : "r"(addr));
}
__device__ __forceinline__ void ldsm4t(uint32_t* r, uint32_t addr) {
    asm volatile("ldmatrix.sync.aligned.m8n8.x4.trans.shared.b16 {%0,%1,%2,%3}, [%4];"
        : "=r"(r[0]), "=r"(r[1]), "=r"(r[2]), "=r"(r[3]) : "r"(addr));
}
__device__ __forceinline__ void mma_bf16(float* c, const uint32_t* a, uint32_t b0, uint32_t b1) {
    asm volatile("mma.sync.aligned.m16n8k16.row.col.f32.bf16.bf16.f32 "
        "{%0,%1,%2,%3}, {%4,%5,%6,%7}, {%8,%9}, {%0,%1,%2,%3};"
        : "+f"(c[0]), "+f"(c[1]), "+f"(c[2]), "+f"(c[3])
        : "r"(a[0]), "r"(a[1]), "r"(a[2]), "r"(a[3]), "r"(b0), "r"(b1));
}

__device__ __forceinline__ void split4(float4 v, uint2& hi, uint2& lo) {
    __nv_bfloat16 h0 = __float2bfloat16(v.x), h1 = __float2bfloat16(v.y);
    __nv_bfloat16 h2 = __float2bfloat16(v.z), h3 = __float2bfloat16(v.w);
    __nv_bfloat162 hp0{h0, h1}, hp1{h2, h3};
    __nv_bfloat162 lp0{__float2bfloat16(v.x - __bfloat162float(h0)),
                       __float2bfloat16(v.y - __bfloat162float(h1))};
    __nv_bfloat162 lp1{__float2bfloat16(v.z - __bfloat162float(h2)),
                       __float2bfloat16(v.w - __bfloat162float(h3))};
    hi = make_uint2(*(uint32_t*)&hp0, *(uint32_t*)&hp1);
    lo = make_uint2(*(uint32_t*)&lp0, *(uint32_t*)&lp1);
}

// expm1 for u in [0,1e-3]: 3 FFMA, no MUFU
__device__ __forceinline__ float expm1_small(float u) {
    return u * fmaf(u, fmaf(u, 0.16666667f, 0.5f), 1.0f);
}
__device__ __forceinline__ uint32_t poly_pack2(float a, float b) {
    __nv_bfloat162 v = __floats2bfloat162_rn(expm1_small(a), expm1_small(b));
    return *(uint32_t*)&v;
}

// ---------------- smem layout ----------------
constexpr int P      = 136;                  // bf16 row pitch (272 B)
constexpr int T1B    = 32 * P * 2;           // 8704 B  (one 32x128 bf16 tile)
constexpr int SLOT1B = 4 * T1B;              // 34816 B (Ahi|Alo|Bhi|Blo), 2 slots
constexpr int ET2B   = 32 * P * 2;           // 8704 B  (E tile)
constexpr int UT2B   = 128 * P * 2;          // 34816 B (u tile, 128 krows x 64 n)
constexpr int STG2B  = ET2B + UT2B;          // 43520 B, 4 stages
constexpr int RED_OFF = 4 * STG2B;           // 174080
constexpr int DSMEM   = RED_OFF + 24576 + 256;  // sred (24.6KB) + srs/rst

// ---------------- grid sync (epoch-based, replay-safe) ----------------
__device__ __forceinline__ void grid_sync(int tid, int nblocks) {
    __syncthreads();
    if (tid == 0) {
        __threadfence();
        unsigned e;
        asm volatile("ld.acquire.gpu.global.b32 %0, [%1];" : "=r"(e) : "l"(&g_epoch) : "memory");
        unsigned arrived = atomicAdd(&g_count, 1u) + 1u;
        if (arrived == (unsigned)nblocks) {
            atomicExch(&g_count, 0u);
            __threadfence();
            atomicAdd(&g_epoch, 1u);
        } else {
            unsigned cur;
            do {
                __nanosleep(64);
                asm volatile("ld.acquire.gpu.global.b32 %0, [%1];" : "=r"(cur) : "l"(&g_epoch) : "memory");
            } while (cur == e);
        }
        __threadfence();
    }
    __syncthreads();
}

// ============================================================
// Fused kernel: phase1 gemm1 (inline split) + u rider -> gridsync -> phase2 gemm2
// 128 CTAs x 512 threads, 1 CTA/SM (smem-bound) -> co-residency guaranteed.
// ============================================================
__global__ __launch_bounds__(512) void fused_kernel(
    const float* __restrict__ x, const float* __restrict__ W,
    const float* __restrict__ u, float* __restrict__ Y)
{
    extern __shared__ __align__(16) char smem[];
    const uint32_t sb = smem_u32(smem);
    float* sredf = (float*)(smem + RED_OFF);

    const int tid = threadIdx.x, lane = tid & 31, wid = tid >> 5;
    const int blk = blockIdx.x;
    const int nt = blk & 15;
    const int m0 = (blk >> 4) * 32, n0 = nt * 32;

    // ---- u rider: issue LDGs first ----
    const int ubase = blk * 1024 + tid * 2;           // float4 index
    float4 uv0 = ((const float4*)u)[ubase];
    float4 uv1 = ((const float4*)u)[ubase + 1];

    // =================== PHASE 1: E = exp(x @ W^T), bf16x3 ===================
    // loader: threads [0,256) -> A (x), [256,512) -> B (W); 16 floats/thread/chunk
    const int half = tid >> 8;
    const int local = tid & 255;
    const int rowL = local >> 3;                      // 0..31
    const int colL = (local & 7) * 16;                // float col
    const float* gsrc = (half ? W + (n0 + rowL) * 1024 : x + (m0 + rowL) * 1024) + colL;
    const uint32_t hiB = (half ? 2 * T1B : 0) + (uint32_t)((rowL * P + colL) * 2);

    float4 va0, va1, va2, va3;
    #define LDG1(c) do { const float* _p = gsrc + (c) * 128; \
        va0 = *(const float4*)_p;       va1 = *(const float4*)(_p + 4); \
        va2 = *(const float4*)(_p + 8); va3 = *(const float4*)(_p + 12); } while (0)
    #define STS1(c) do { \
        char* _d = smem + ((c) & 1) * SLOT1B + hiB; \
        uint2 h0, l0, h1, l1, h2, l2, h3, l3; \
        split4(va0, h0, l0); split4(va1, h1, l1); \
        split4(va2, h2, l2); split4(va3, h3, l3); \
        *(uint4*)(_d)            = make_uint4(h0.x, h0.y, h1.x, h1.y); \
        *(uint4*)(_d + 16)       = make_uint4(h2.x, h2.y, h3.x, h3.y); \
        *(uint4*)(_d + T1B)      = make_uint4(l0.x, l0.y, l1.x, l1.y); \
        *(uint4*)(_d + T1B + 16) = make_uint4(l2.x, l2.y, l3.x, l3.y); \
    } while (0)

    // compute mapping: 16 warps = 2(wn) x 2(wm) x 4(wk)
    const int wn = wid & 1, wm = (wid >> 1) & 1, wk = wid >> 2;
    const int lrow = lane & 15;
    const int lk = (lane >> 4) << 3;
    const uint32_t aOff = (uint32_t)(((wm * 16 + lrow) * P + lk) * 2);
    const uint32_t bOff = (uint32_t)(((wn * 16 + lrow) * P + lk) * 2);

    float hh0[4] = {}, hh1[4] = {}, hl0[4] = {}, hl1[4] = {}, lh0[4] = {}, lh1[4] = {};

    LDG1(0);
    // u rider: convert + store while LDG(0) is in flight
    *(uint2*)&g_ub[ubase * 4]     = make_uint2(poly_pack2(uv0.x, uv0.y), poly_pack2(uv0.z, uv0.w));
    *(uint2*)&g_ub[ubase * 4 + 4] = make_uint2(poly_pack2(uv1.x, uv1.y), poly_pack2(uv1.z, uv1.w));

    for (int c = 0; c < 8; c++) {
        STS1(c);
        if (c < 7) LDG1(c + 1);
        __syncthreads();
        const uint32_t st = sb + (c & 1) * SLOT1B;
        #pragma unroll
        for (int j = 0; j < 2; j++) {
            const int ks = wk * 2 + j;               // 0..7 ksteps of 16
            uint32_t a_hi[4], a_lo[4], b_hi[4], b_lo[4];
            ldsm4(a_hi, st + aOff + ks * 32);
            ldsm4(a_lo, st + T1B + aOff + ks * 32);
            ldsm4(b_hi, st + 2 * T1B + bOff + ks * 32);
            ldsm4(b_lo, st + 3 * T1B + bOff + ks * 32);
            mma_bf16(hh0, a_hi, b_hi[0], b_hi[2]);
            mma_bf16(hh1, a_hi, b_hi[1], b_hi[3]);
            mma_bf16(hl0, a_hi, b_lo[0], b_lo[2]);
            mma_bf16(hl1, a_hi, b_lo[1], b_lo[3]);
            mma_bf16(lh0, a_lo, b_hi[0], b_hi[2]);
            mma_bf16(lh1, a_lo, b_hi[1], b_hi[3]);
        }
    }
    #undef LDG1
    #undef STS1

    float acc0[4], acc1[4];
    #pragma unroll
    for (int i = 0; i < 4; i++) {
        acc0[i] = hh0[i] + hl0[i] + lh0[i];
        acc1[i] = hh1[i] + hl1[i] + lh1[i];
    }

    // 4-way k-split reduction: sred1[12][32][8]
    float (*sred1)[32][8] = (float(*)[32][8])sredf;
    float (*srs)[32] = (float(*)[32])(smem + RED_OFF + 12288);
    __syncthreads();
    if (wk != 0) {
        #pragma unroll
        for (int i = 0; i < 4; i++) {
            sred1[(wk - 1) * 4 + (wid & 3)][lane][i]     = acc0[i];
            sred1[(wk - 1) * 4 + (wid & 3)][lane][4 + i] = acc1[i];
        }
    }
    __syncthreads();

    if (wk == 0) {
        #pragma unroll
        for (int q = 0; q < 3; q++)
            #pragma unroll
            for (int i = 0; i < 4; i++) {
                acc0[i] += sred1[q * 4 + wid][lane][i];
                acc1[i] += sred1[q * 4 + wid][lane][4 + i];
            }
        // epilogue: exp, bf16 E, fp32 rowsum
        const int qr = lane >> 2;
        const int qc = (lane & 3) * 2;
        const int mrow0 = m0 + wm * 16 + qr;
        const int mrow1 = mrow0 + 8;
        float p0 = 0.f, p1 = 0.f;
        #pragma unroll
        for (int g = 0; g < 2; g++) {
            float* acc = g ? acc1 : acc0;
            float e0 = expf(acc[0]), e1 = expf(acc[1]);
            float e2 = expf(acc[2]), e3 = expf(acc[3]);
            p0 += e0 + e1; p1 += e2 + e3;
            const int n = n0 + wn * 16 + g * 8 + qc;
            __nv_bfloat162 v0 = __floats2bfloat162_rn(e0, e1);
            __nv_bfloat162 v1 = __floats2bfloat162_rn(e2, e3);
            *(uint32_t*)&g_Ebf[mrow0 * 512 + n] = *(uint32_t*)&v0;
            *(uint32_t*)&g_Ebf[mrow1 * 512 + n] = *(uint32_t*)&v1;
        }
        p0 += __shfl_xor_sync(0xFFFFFFFFu, p0, 1);
        p0 += __shfl_xor_sync(0xFFFFFFFFu, p0, 2);
        p1 += __shfl_xor_sync(0xFFFFFFFFu, p1, 1);
        p1 += __shfl_xor_sync(0xFFFFFFFFu, p1, 2);
        if ((lane & 3) == 0) {
            srs[wn][wm * 16 + qr]     = p0;
            srs[wn][wm * 16 + qr + 8] = p1;
        }
    }
    __syncthreads();
    if (tid < 32) g_rs[nt * 256 + m0 + tid] = srs[0][tid] + srs[1][tid];

    // =================== GRID SYNC ===================
    grid_sync(tid, (int)gridDim.x);

    // =================== PHASE 2: y = E @ g_ub + rowsum + 512 ===================
    const int n0b = nt * 64;                          // gemm2 n-tile (32M x 64N)

    float* rst = (float*)(smem + RED_OFF + 24576);
    if (tid < 32) {
        float s = 512.0f;
        #pragma unroll
        for (int j = 0; j < 16; j++) s += g_rs[j * 256 + m0 + tid];
        rst[tid] = s;
    }

    // loaders
    const int rowE = tid >> 4, segE = tid & 15;
    const __nv_bfloat16* aSrc = g_Ebf + (m0 + rowE) * 512 + segE * 8;
    const uint32_t aDst = sb + (uint32_t)((rowE * P + segE * 8) * 2);
    const int uIdx0 = tid * 2, uIdx1 = tid * 2 + 1;
    const int kr0 = uIdx0 >> 3, sg0 = uIdx0 & 7;
    const int kr1 = uIdx1 >> 3, sg1 = uIdx1 & 7;
    const __nv_bfloat16* bSrc0 = g_ub + kr0 * 1024 + n0b + sg0 * 8;
    const __nv_bfloat16* bSrc1 = g_ub + kr1 * 1024 + n0b + sg1 * 8;
    const uint32_t bDst0 = sb + (uint32_t)(ET2B + (kr0 * P + sg0 * 8) * 2);
    const uint32_t bDst1 = sb + (uint32_t)(ET2B + (kr1 * P + sg1 * 8) * 2);

    #define G2_ISSUE(c) do { \
        const uint32_t _so = (c) * STG2B; \
        cp16(aDst + _so, aSrc + (c) * 128); \
        cp16(bDst0 + _so, bSrc0 + (c) * 128 * 1024); \
        cp16(bDst1 + _so, bSrc1 + (c) * 128 * 1024); \
        CP_COMMIT(); \
    } while (0)

    // trans-B compute mapping
    const uint32_t a2Off = (uint32_t)(((wm * 16 + lrow) * P + lk) * 2);
    const int li = lane & 7, kbit = (lane >> 3) & 1, nq = lane >> 4;
    const uint32_t tOff = (uint32_t)((((kbit * 8 + li) * P) + nq * 8) * 2);

    float acc[4][4] = {};

    G2_ISSUE(0); G2_ISSUE(1); G2_ISSUE(2); G2_ISSUE(3);

    #pragma unroll
    for (int c = 0; c < 4; c++) {
        if (c == 0) CP_WAITN(3);
        else if (c == 1) CP_WAITN(2);
        else if (c == 2) CP_WAITN(1);
        else CP_WAITN(0);
        __syncthreads();
        const uint32_t st = sb + c * STG2B;
        const uint32_t stU = st + ET2B;
        #pragma unroll
        for (int j = 0; j < 2; j++) {
            const int ks = wk * 2 + j;
            uint32_t a[4], bq0[4], bq1[4];
            ldsm4(a, st + a2Off + ks * 32);
            ldsm4t(bq0, stU + tOff + ks * 16 * P * 2 + (wn * 32 + 0) * 2);
            ldsm4t(bq1, stU + tOff + ks * 16 * P * 2 + (wn * 32 + 16) * 2);
            mma_bf16(acc[0], a, bq0[0], bq0[1]);
            mma_bf16(acc[1], a, bq0[2], bq0[3]);
            mma_bf16(acc[2], a, bq1[0], bq1[1]);
            mma_bf16(acc[3], a, bq1[2], bq1[3]);
        }
    }
    #undef G2_ISSUE

    // k-split reduction: sred2[12][32][16]
    float (*sred2)[32][16] = (float(*)[32][16])sredf;
    __syncthreads();
    if (wk != 0) {
        #pragma unroll
        for (int g = 0; g < 4; g++)
            #pragma unroll
            for (int i = 0; i < 4; i++)
                sred2[(wk - 1) * 4 + (wid & 3)][lane][g * 4 + i] = acc[g][i];
    }
    __syncthreads();

    if (wk == 0) {
        #pragma unroll
        for (int q = 0; q < 3; q++)
            #pragma unroll
            for (int g = 0; g < 4; g++)
                #pragma unroll
                for (int i = 0; i < 4; i++)
                    acc[g][i] += sred2[q * 4 + wid][lane][g * 4 + i];

        const int qr = lane >> 2;
        const int qc = (lane & 3) * 2;
        const int mrow0 = m0 + wm * 16 + qr;
        const int mrow1 = mrow0 + 8;
        const float r0v = rst[wm * 16 + qr];
        const float r1v = rst[wm * 16 + qr + 8];
        #pragma unroll
        for (int g = 0; g < 4; g++) {
            const int n = n0b + wn * 32 + g * 8 + qc;
            *(float2*)(Y + mrow0 * 1024 + n) = make_float2(acc[g][0] + r0v, acc[g][1] + r0v);
            *(float2*)(Y + mrow1 * 1024 + n) = make_float2(acc[g][2] + r1v, acc[g][3] + r1v);
        }
    }
}

// ============================================================
extern "C" void kernel_launch(void* const* d_in, const int* in_sizes, int n_in,
                              void* d_out, int out_size)
{
    const float* x = (const float*)d_in[0];   // 256 x 1024
    const float* W = (const float*)d_in[1];   // 512 x 1024
    const float* u = (const float*)d_in[2];   // 512 x 1024
    float* y = (float*)d_out;                 // 256 x 1024

    cudaFuncSetAttribute(fused_kernel, cudaFuncAttributeMaxDynamicSharedMemorySize, DSMEM);
    fused_kernel<<<128, 512, DSMEM>>>(x, W, u, y);
}

// round 10
// speedup vs baseline: 1.0943x; 1.0875x over previous
#include <cuda_runtime.h>
#include <cuda_fp16.h>
#include <cstdint>
#include <math.h>

// ---------------- device scratch (allocation-free) ----------------
__device__ __align__(16) __half g_ub [512 * 1024];   // fp16(expm1(u[k][n])), [k][n]
__device__ __align__(16) __half g_Ef [256 * 512];    // fp16(E)
__device__ float g_rs[16 * 256];                     // per-(ntile,row) rowsums of E
__device__ unsigned g_count = 0;                     // grid-sync arrivals
__device__ unsigned g_epoch = 0;                     // grid-sync epoch (monotonic)

// ---------------- helpers ----------------
__device__ __forceinline__ uint32_t smem_u32(const void* p) {
    uint32_t a;
    asm("{ .reg .u64 t; cvta.to.shared.u64 t, %1; cvt.u32.u64 %0, t; }" : "=r"(a) : "l"(p));
    return a;
}
__device__ __forceinline__ void cp16(uint32_t dst, const void* src) {
    asm volatile("cp.async.cg.shared.global [%0], [%1], 16;" :: "r"(dst), "l"(src) : "memory");
}
#define CP_COMMIT() asm volatile("cp.async.commit_group;" ::: "memory")
#define CP_WAITN(n) asm volatile("cp.async.wait_group %0;" :: "n"(n) : "memory")

__device__ __forceinline__ void ldsm4(uint32_t* r, uint32_t addr) {
    asm volatile("ldmatrix.sync.aligned.m8n8.x4.shared.b16 {%0,%1,%2,%3}, [%4];"
        : "=r"(r[0]), "=r"(r[1]), "=r"(r[2]), "=r"(r[3]) : "r"(addr));
}
__device__ __forceinline__ void ldsm4t(uint32_t* r, uint32_t addr) {
    asm volatile("ldmatrix.sync.aligned.m8n8.x4.trans.shared.b16 {%0,%1,%2,%3}, [%4];"
        : "=r"(r[0]), "=r"(r[1]), "=r"(r[2]), "=r"(r[3]) : "r"(addr));
}
__device__ __forceinline__ void mma_f16(float* c, const uint32_t* a, uint32_t b0, uint32_t b1) {
    asm volatile("mma.sync.aligned.m16n8k16.row.col.f32.f16.f16.f32 "
        "{%0,%1,%2,%3}, {%4,%5,%6,%7}, {%8,%9}, {%0,%1,%2,%3};"
        : "+f"(c[0]), "+f"(c[1]), "+f"(c[2]), "+f"(c[3])
        : "r"(a[0]), "r"(a[1]), "r"(a[2]), "r"(a[3]), "r"(b0), "r"(b1));
}

__device__ __forceinline__ uint32_t pack_h2(float a, float b) {
    __half2 h = __floats2half2_rn(a, b);
    return *(uint32_t*)&h;
}

// expm1 for u in [0,1e-3]: 3 FFMA, no MUFU
__device__ __forceinline__ float expm1_small(float u) {
    return u * fmaf(u, fmaf(u, 0.16666667f, 0.5f), 1.0f);
}
__device__ __forceinline__ uint32_t poly_pack2(float a, float b) {
    return pack_h2(expm1_small(a), expm1_small(b));
}

// ---------------- smem layout ----------------
constexpr int P      = 136;                  // 16-bit elem row pitch (272 B)
constexpr int T1B    = 32 * P * 2;           // 8704 B  (one 32x128 f16 tile)
constexpr int SLOT1B = 2 * T1B;              // 17408 B (A|B), 2 slots
constexpr int ET2B   = 32 * P * 2;           // 8704 B  (E tile)
constexpr int UT2B   = 128 * P * 2;          // 34816 B (u tile, 128 krows x 64 n)
constexpr int STG2B  = ET2B + UT2B;          // 43520 B, 4 stages
constexpr int RED_OFF = 4 * STG2B;           // 174080
constexpr int DSMEM   = RED_OFF + 24576 + 256;

// ---------------- grid sync (epoch-based, replay-safe) ----------------
__device__ __forceinline__ void grid_sync(int tid, int nblocks) {
    __syncthreads();
    if (tid == 0) {
        __threadfence();
        unsigned e;
        asm volatile("ld.acquire.gpu.global.b32 %0, [%1];" : "=r"(e) : "l"(&g_epoch) : "memory");
        unsigned arrived = atomicAdd(&g_count, 1u) + 1u;
        if (arrived == (unsigned)nblocks) {
            atomicExch(&g_count, 0u);
            __threadfence();
            atomicAdd(&g_epoch, 1u);
        } else {
            unsigned cur;
            do {
                __nanosleep(64);
                asm volatile("ld.acquire.gpu.global.b32 %0, [%1];" : "=r"(cur) : "l"(&g_epoch) : "memory");
            } while (cur == e);
        }
        __threadfence();
    }
    __syncthreads();
}

// ============================================================
// Fused: phase1 E=exp(x@W^T) in single-pass fp16 + u rider
//        -> gridsync -> phase2 y = E @ expm1(u) + rowsum + 512
// 128 CTAs x 512 thr (16 warps: 2 wn x 2 wm x 4 wk), 1 CTA/SM.
// ============================================================
__global__ __launch_bounds__(512) void fused_kernel(
    const float* __restrict__ x, const float* __restrict__ W,
    const float* __restrict__ u, float* __restrict__ Y)
{
    extern __shared__ __align__(16) char smem[];
    const uint32_t sb = smem_u32(smem);
    float* sredf = (float*)(smem + RED_OFF);

    const int tid = threadIdx.x, lane = tid & 31, wid = tid >> 5;
    const int blk = blockIdx.x;
    const int nt = blk & 15;
    const int m0 = (blk >> 4) * 32, n0 = nt * 32;

    // ---- u rider: issue LDGs first ----
    const int ubase = blk * 1024 + tid * 2;           // float4 index
    float4 uv0 = ((const float4*)u)[ubase];
    float4 uv1 = ((const float4*)u)[ubase + 1];

    // =================== PHASE 1 ===================
    // loader: threads [0,256) -> A (x rows m0..m0+31), [256,512) -> B (W rows n0..n0+31)
    // 16 floats/thread/chunk (K=128 chunks)
    const int hf = tid >> 8;
    const int local = tid & 255;
    const int rowL = local >> 3;                      // 0..31
    const int colL = (local & 7) * 16;                // float col
    const float* gsrc = (hf ? W + (n0 + rowL) * 1024 : x + (m0 + rowL) * 1024) + colL;
    const uint32_t dstB = (hf ? T1B : 0) + (uint32_t)((rowL * P + colL) * 2);

    float4 va0, va1, va2, va3;
    #define LDG1(c) do { const float* _p = gsrc + (c) * 128; \
        va0 = *(const float4*)_p;       va1 = *(const float4*)(_p + 4); \
        va2 = *(const float4*)(_p + 8); va3 = *(const float4*)(_p + 12); } while (0)
    #define STS1(c) do { \
        char* _d = smem + ((c) & 1) * SLOT1B + dstB; \
        *(uint4*)(_d)      = make_uint4(pack_h2(va0.x, va0.y), pack_h2(va0.z, va0.w), \
                                        pack_h2(va1.x, va1.y), pack_h2(va1.z, va1.w)); \
        *(uint4*)(_d + 16) = make_uint4(pack_h2(va2.x, va2.y), pack_h2(va2.z, va2.w), \
                                        pack_h2(va3.x, va3.y), pack_h2(va3.z, va3.w)); \
    } while (0)

    // compute mapping: 16 warps = 2(wn) x 2(wm) x 4(wk)
    const int wn = wid & 1, wm = (wid >> 1) & 1, wk = wid >> 2;
    const int lrow = lane & 15;
    const int lk = (lane >> 4) << 3;
    const uint32_t aOff = (uint32_t)(((wm * 16 + lrow) * P + lk) * 2);
    const uint32_t bOff = (uint32_t)(T1B + ((wn * 16 + lrow) * P + lk) * 2);

    float acc0[4] = {}, acc1[4] = {};

    LDG1(0);
    // u rider: convert + store while LDG(0) is in flight
    *(uint2*)&g_ub[ubase * 4]     = make_uint2(poly_pack2(uv0.x, uv0.y), poly_pack2(uv0.z, uv0.w));
    *(uint2*)&g_ub[ubase * 4 + 4] = make_uint2(poly_pack2(uv1.x, uv1.y), poly_pack2(uv1.z, uv1.w));

    for (int c = 0; c < 8; c++) {
        STS1(c);
        if (c < 7) LDG1(c + 1);
        __syncthreads();
        const uint32_t st = sb + (c & 1) * SLOT1B;
        #pragma unroll
        for (int j = 0; j < 2; j++) {
            const int ks = wk * 2 + j;               // 0..7 ksteps of 16
            uint32_t a[4], b[4];
            ldsm4(a, st + aOff + ks * 32);
            ldsm4(b, st + bOff + ks * 32);
            mma_f16(acc0, a, b[0], b[2]);
            mma_f16(acc1, a, b[1], b[3]);
        }
        __syncthreads();
    }
    #undef LDG1
    #undef STS1

    // 4-way k-split reduction: sred1[12][32][8]
    float (*sred1)[32][8] = (float(*)[32][8])sredf;
    float (*srs)[32] = (float(*)[32])(smem + RED_OFF + 12288);
    if (wk != 0) {
        #pragma unroll
        for (int i = 0; i < 4; i++) {
            sred1[(wk - 1) * 4 + (wid & 3)][lane][i]     = acc0[i];
            sred1[(wk - 1) * 4 + (wid & 3)][lane][4 + i] = acc1[i];
        }
    }
    __syncthreads();

    if (wk == 0) {
        #pragma unroll
        for (int q = 0; q < 3; q++)
            #pragma unroll
            for (int i = 0; i < 4; i++) {
                acc0[i] += sred1[q * 4 + wid][lane][i];
                acc1[i] += sred1[q * 4 + wid][lane][4 + i];
            }
        // epilogue: exp, fp16 E, fp32 rowsum
        const int qr = lane >> 2;
        const int qc = (lane & 3) * 2;
        const int mrow0 = m0 + wm * 16 + qr;
        const int mrow1 = mrow0 + 8;
        float p0 = 0.f, p1 = 0.f;
        #pragma unroll
        for (int g = 0; g < 2; g++) {
            float* acc = g ? acc1 : acc0;
            float e0 = expf(acc[0]), e1 = expf(acc[1]);
            float e2 = expf(acc[2]), e3 = expf(acc[3]);
            p0 += e0 + e1; p1 += e2 + e3;
            const int n = n0 + wn * 16 + g * 8 + qc;
            *(uint32_t*)&g_Ef[mrow0 * 512 + n] = pack_h2(e0, e1);
            *(uint32_t*)&g_Ef[mrow1 * 512 + n] = pack_h2(e2, e3);
        }
        p0 += __shfl_xor_sync(0xFFFFFFFFu, p0, 1);
        p0 += __shfl_xor_sync(0xFFFFFFFFu, p0, 2);
        p1 += __shfl_xor_sync(0xFFFFFFFFu, p1, 1);
        p1 += __shfl_xor_sync(0xFFFFFFFFu, p1, 2);
        if ((lane & 3) == 0) {
            srs[wn][wm * 16 + qr]     = p0;
            srs[wn][wm * 16 + qr + 8] = p1;
        }
    }
    __syncthreads();
    if (tid < 32) g_rs[nt * 256 + m0 + tid] = srs[0][tid] + srs[1][tid];

    // =================== GRID SYNC ===================
    grid_sync(tid, (int)gridDim.x);

    // =================== PHASE 2 ===================
    const int n0b = nt * 64;

    float* rst = (float*)(smem + RED_OFF + 24576);
    if (tid < 32) {
        float s = 512.0f;
        #pragma unroll
        for (int j = 0; j < 16; j++) s += g_rs[j * 256 + m0 + tid];
        rst[tid] = s;
    }

    // loaders: E 1 cp16/thread, u 2 cp16/thread per chunk (K=128 chunks)
    const int rowE = tid >> 4, segE = tid & 15;
    const __half* aSrc = g_Ef + (m0 + rowE) * 512 + segE * 8;
    const uint32_t aDst = sb + (uint32_t)((rowE * P + segE * 8) * 2);
    const int uIdx0 = tid * 2, uIdx1 = tid * 2 + 1;
    const int kr0 = uIdx0 >> 3, sg0 = uIdx0 & 7;
    const int kr1 = uIdx1 >> 3, sg1 = uIdx1 & 7;
    const __half* bSrc0 = g_ub + kr0 * 1024 + n0b + sg0 * 8;
    const __half* bSrc1 = g_ub + kr1 * 1024 + n0b + sg1 * 8;
    const uint32_t bDst0 = sb + (uint32_t)(ET2B + (kr0 * P + sg0 * 8) * 2);
    const uint32_t bDst1 = sb + (uint32_t)(ET2B + (kr1 * P + sg1 * 8) * 2);

    #define G2_ISSUE(c) do { \
        const uint32_t _so = (c) * STG2B; \
        cp16(aDst + _so, aSrc + (c) * 128); \
        cp16(bDst0 + _so, bSrc0 + (c) * 128 * 1024); \
        cp16(bDst1 + _so, bSrc1 + (c) * 128 * 1024); \
        CP_COMMIT(); \
    } while (0)

    const uint32_t a2Off = (uint32_t)(((wm * 16 + lrow) * P + lk) * 2);
    const int li = lane & 7, kbit = (lane >> 3) & 1, nq = lane >> 4;
    const uint32_t tOff = (uint32_t)((((kbit * 8 + li) * P) + nq * 8) * 2);

    float acc[4][4] = {};

    G2_ISSUE(0); G2_ISSUE(1); G2_ISSUE(2); G2_ISSUE(3);

    #pragma unroll
    for (int c = 0; c < 4; c++) {
        if (c == 0) CP_WAITN(3);
        else if (c == 1) CP_WAITN(2);
        else if (c == 2) CP_WAITN(1);
        else CP_WAITN(0);
        __syncthreads();
        const uint32_t st = sb + c * STG2B;
        const uint32_t stU = st + ET2B;
        #pragma unroll
        for (int j = 0; j < 2; j++) {
            const int ks = wk * 2 + j;
            uint32_t a[4], bq0[4], bq1[4];
            ldsm4(a, st + a2Off + ks * 32);
            ldsm4t(bq0, stU + tOff + ks * 16 * P * 2 + (wn * 32 + 0) * 2);
            ldsm4t(bq1, stU + tOff + ks * 16 * P * 2 + (wn * 32 + 16) * 2);
            mma_f16(acc[0], a, bq0[0], bq0[1]);
            mma_f16(acc[1], a, bq0[2], bq0[3]);
            mma_f16(acc[2], a, bq1[0], bq1[1]);
            mma_f16(acc[3], a, bq1[2], bq1[3]);
        }
    }
    #undef G2_ISSUE

    // k-split reduction: sred2[12][32][16]
    float (*sred2)[32][16] = (float(*)[32][16])sredf;
    __syncthreads();
    if (wk != 0) {
        #pragma unroll
        for (int g = 0; g < 4; g++)
            #pragma unroll
            for (int i = 0; i < 4; i++)
                sred2[(wk - 1) * 4 + (wid & 3)][lane][g * 4 + i] = acc[g][i];
    }
    __syncthreads();

    if (wk == 0) {
        #pragma unroll
        for (int q = 0; q < 3; q++)
            #pragma unroll
            for (int g = 0; g < 4; g++)
                #pragma unroll
                for (int i = 0; i < 4; i++)
                    acc[g][i] += sred2[q * 4 + wid][lane][g * 4 + i];

        const int qr = lane >> 2;
        const int qc = (lane & 3) * 2;
        const int mrow0 = m0 + wm * 16 + qr;
        const int mrow1 = mrow0 + 8;
        const float r0v = rst[wm * 16 + qr];
        const float r1v = rst[wm * 16 + qr + 8];
        #pragma unroll
        for (int g = 0; g < 4; g++) {
            const int n = n0b + wn * 32 + g * 8 + qc;
            *(float2*)(Y + mrow0 * 1024 + n) = make_float2(acc[g][0] + r0v, acc[g][1] + r0v);
            *(float2*)(Y + mrow1 * 1024 + n) = make_float2(acc[g][2] + r1v, acc[g][3] + r1v);
        }
    }
}

// ============================================================
extern "C" void kernel_launch(void* const* d_in, const int* in_sizes, int n_in,
                              void* d_out, int out_size)
{
    const float* x = (const float*)d_in[0];   // 256 x 1024
    const float* W = (const float*)d_in[1];   // 512 x 1024
    const float* u = (const float*)d_in[2];   // 512 x 1024
    float* y = (float*)d_out;                 // 256 x 1024

    cudaFuncSetAttribute(fused_kernel, cudaFuncAttributeMaxDynamicSharedMemorySize, DSMEM);
    fused_kernel<<<128, 512, DSMEM>>>(x, W, u, y);
}

// round 12
// speedup vs baseline: 1.1993x; 1.0959x over previous
#include <cuda_runtime.h>
#include <cuda_fp16.h>
#include <cstdint>
#include <math.h>

// ---------------- device scratch (allocation-free) ----------------
__device__ __align__(16) __half g_xh [256 * 1024];   // fp16(x)
__device__ __align__(16) __half g_Wh [512 * 1024];   // fp16(W)
__device__ __align__(16) __half g_ub [512 * 1024];   // fp16(expm1(u[k][n])), [k][n]
__device__ __align__(16) __half g_Ef [256 * 512];    // fp16(E)
__device__ float g_rs[16 * 256];                     // per-(ntile,row) rowsums of E
__device__ unsigned g_count = 0;                     // grid-sync arrivals
__device__ unsigned g_epoch = 0;                     // grid-sync epoch (monotonic)

// ---------------- helpers ----------------
__device__ __forceinline__ uint32_t smem_u32(const void* p) {
    uint32_t a;
    asm("{ .reg .u64 t; cvta.to.shared.u64 t, %1; cvt.u32.u64 %0, t; }" : "=r"(a) : "l"(p));
    return a;
}
__device__ __forceinline__ void cp16(uint32_t dst, const void* src) {
    asm volatile("cp.async.cg.shared.global [%0], [%1], 16;" :: "r"(dst), "l"(src) : "memory");
}
#define CP_COMMIT() asm volatile("cp.async.commit_group;" ::: "memory")
#define CP_WAITN(n) asm volatile("cp.async.wait_group %0;" :: "n"(n) : "memory")

__device__ __forceinline__ void ldsm4(uint32_t* r, uint32_t addr) {
    asm volatile("ldmatrix.sync.aligned.m8n8.x4.shared.b16 {%0,%1,%2,%3}, [%4];"
        : "=r"(r[0]), "=r"(r[1]), "=r"(r[2]), "=r"(r[3]) : "r"(addr));
}
__device__ __forceinline__ void ldsm4t(uint32_t* r, uint32_t addr) {
    asm volatile("ldmatrix.sync.aligned.m8n8.x4.trans.shared.b16 {%0,%1,%2,%3}, [%4];"
        : "=r"(r[0]), "=r"(r[1]), "=r"(r[2]), "=r"(r[3]) : "r"(addr));
}
__device__ __forceinline__ void mma_f16(float* c, const uint32_t* a, uint32_t b0, uint32_t b1) {
    asm volatile("mma.sync.aligned.m16n8k16.row.col.f32.f16.f16.f32 "
        "{%0,%1,%2,%3}, {%4,%5,%6,%7}, {%8,%9}, {%0,%1,%2,%3};"
        : "+f"(c[0]), "+f"(c[1]), "+f"(c[2]), "+f"(c[3])
        : "r"(a[0]), "r"(a[1]), "r"(a[2]), "r"(a[3]), "r"(b0), "r"(b1));
}

__device__ __forceinline__ uint32_t pack_h2(float a, float b) {
    __half2 h = __floats2half2_rn(a, b);
    return *(uint32_t*)&h;
}
// expm1 for u in [0,1e-3]: 3 FFMA, no MUFU
__device__ __forceinline__ float expm1_small(float u) {
    return u * fmaf(u, fmaf(u, 0.16666667f, 0.5f), 1.0f);
}
__device__ __forceinline__ uint32_t poly_pack2(float a, float b) {
    return pack_h2(expm1_small(a), expm1_small(b));
}

// ---------------- smem layout ----------------
constexpr int P      = 136;                  // 16-bit elem row pitch (272 B)
constexpr int T1B    = 32 * P * 2;           // 8704 B  (one 32x128 f16 tile)
constexpr int STG1B  = 2 * T1B;              // 17408 B (A|B), 4 stages = 69632
constexpr int ET2B   = 32 * P * 2;           // 8704 B
constexpr int UT2B   = 128 * P * 2;          // 34816 B
constexpr int STG2B  = ET2B + UT2B;          // 43520 B, 4 stages = 174080
constexpr int RED_OFF = 4 * STG2B;           // 174080
constexpr int DSMEM   = RED_OFF + 24576 + 256;

// ---------------- grid sync (epoch-based, replay-safe) ----------------
__device__ __forceinline__ void grid_sync(int tid, int nblocks) {
    __syncthreads();
    if (tid == 0) {
        __threadfence();
        unsigned e;
        asm volatile("ld.acquire.gpu.global.b32 %0, [%1];" : "=r"(e) : "l"(&g_epoch) : "memory");
        unsigned arrived = atomicAdd(&g_count, 1u) + 1u;
        if (arrived == (unsigned)nblocks) {
            atomicExch(&g_count, 0u);
            __threadfence();
            atomicAdd(&g_epoch, 1u);
        } else {
            unsigned cur;
            do {
                __nanosleep(64);
                asm volatile("ld.acquire.gpu.global.b32 %0, [%1];" : "=r"(cur) : "l"(&g_epoch) : "memory");
            } while (cur == e);
        }
        __threadfence();
    }
    __syncthreads();
}

// ============================================================
// Fused, 3 phases:
//  P0: convert x,W -> f16; u -> f16(expm1)    (coalesced, MLP=5)
//  P1: E = exp(x@W^T)  pure cp.async fp16 GEMM (4-stage)
//  P2: y = E @ ub + rowsum(E) + 512            (4-stage, ldsm.trans B)
// 128 CTAs x 512 thr (16 warps: 2wn x 2wm x 4wk), 1 CTA/SM.
// ============================================================
__global__ __launch_bounds__(512) void fused_kernel(
    const float* __restrict__ x, const float* __restrict__ W,
    const float* __restrict__ u, float* __restrict__ Y)
{
    extern __shared__ __align__(16) char smem[];
    const uint32_t sb = smem_u32(smem);
    float* sredf = (float*)(smem + RED_OFF);

    const int tid = threadIdx.x, lane = tid & 31, wid = tid >> 5;
    const int blk = blockIdx.x;
    const int nt = blk & 15;
    const int m0 = (blk >> 4) * 32, n0 = nt * 32;

    // =================== PHASE 0: convert ===================
    {
        const int g = blk * 512 + tid;                    // 0..65535
        float4 xv  = ((const float4*)x)[g];
        float4 wv0 = ((const float4*)W)[g];
        float4 wv1 = ((const float4*)W)[g + 65536];
        float4 uv0 = ((const float4*)u)[g];
        float4 uv1 = ((const float4*)u)[g + 65536];
        *(uint2*)&g_xh[g * 4] = make_uint2(pack_h2(xv.x, xv.y), pack_h2(xv.z, xv.w));
        *(uint2*)&g_Wh[g * 4] = make_uint2(pack_h2(wv0.x, wv0.y), pack_h2(wv0.z, wv0.w));
        *(uint2*)&g_Wh[(g + 65536) * 4] = make_uint2(pack_h2(wv1.x, wv1.y), pack_h2(wv1.z, wv1.w));
        *(uint2*)&g_ub[g * 4] = make_uint2(poly_pack2(uv0.x, uv0.y), poly_pack2(uv0.z, uv0.w));
        *(uint2*)&g_ub[(g + 65536) * 4] = make_uint2(poly_pack2(uv1.x, uv1.y), poly_pack2(uv1.z, uv1.w));
    }
    grid_sync(tid, (int)gridDim.x);

    // =================== PHASE 1: E = exp(x @ W^T) ===================
    // loader: 2 cp16/thread/chunk (A: 32x128 f16 tile, B: same)
    const int rowT = tid >> 4;                 // 0..31
    const int segT = tid & 15;                 // 16B segment
    const __half* aS = g_xh + (m0 + rowT) * 1024 + segT * 8;
    const __half* bS = g_Wh + (n0 + rowT) * 1024 + segT * 8;
    const uint32_t aD = sb + (uint32_t)((rowT * P + segT * 8) * 2);
    const uint32_t bD = sb + (uint32_t)(T1B + (rowT * P + segT * 8) * 2);

    #define G1_ISSUE(c) do { \
        const uint32_t _so = ((c) & 3) * STG1B; \
        cp16(aD + _so, aS + (c) * 128); \
        cp16(bD + _so, bS + (c) * 128); \
        CP_COMMIT(); \
    } while (0)

    // compute mapping: 16 warps = 2(wn) x 2(wm) x 4(wk)
    const int wn = wid & 1, wm = (wid >> 1) & 1, wk = wid >> 2;
    const int lrow = lane & 15;
    const int lk = (lane >> 4) << 3;
    const uint32_t aOff = (uint32_t)(((wm * 16 + lrow) * P + lk) * 2);
    const uint32_t bOff = (uint32_t)(T1B + ((wn * 16 + lrow) * P + lk) * 2);

    float acc0[4] = {}, acc1[4] = {};

    G1_ISSUE(0); G1_ISSUE(1); G1_ISSUE(2);

    for (int c = 0; c < 8; c++) {
        if (c <= 5) CP_WAITN(2);
        else if (c == 6) CP_WAITN(1);
        else CP_WAITN(0);
        __syncthreads();
        if (c + 3 < 8) G1_ISSUE(c + 3);
        const uint32_t st = sb + (c & 3) * STG1B;          // FIXED: + sb
        #pragma unroll
        for (int j = 0; j < 2; j++) {
            const int ks = wk * 2 + j;         // 0..7 ksteps of 16
            uint32_t a[4], b[4];
            ldsm4(a, st + aOff + ks * 32);
            ldsm4(b, st + bOff + ks * 32);
            mma_f16(acc0, a, b[0], b[2]);
            mma_f16(acc1, a, b[1], b[3]);
        }
    }
    #undef G1_ISSUE

    // 4-way k-split reduction: sred1[12][32][8]
    float (*sred1)[32][8] = (float(*)[32][8])sredf;
    float (*srs)[32] = (float(*)[32])(smem + RED_OFF + 12288);
    __syncthreads();
    if (wk != 0) {
        #pragma unroll
        for (int i = 0; i < 4; i++) {
            sred1[(wk - 1) * 4 + (wid & 3)][lane][i]     = acc0[i];
            sred1[(wk - 1) * 4 + (wid & 3)][lane][4 + i] = acc1[i];
        }
    }
    __syncthreads();

    if (wk == 0) {
        #pragma unroll
        for (int q = 0; q < 3; q++)
            #pragma unroll
            for (int i = 0; i < 4; i++) {
                acc0[i] += sred1[q * 4 + wid][lane][i];
                acc1[i] += sred1[q * 4 + wid][lane][4 + i];
            }
        // epilogue: __expf, fp16 E, fp32 rowsum
        const int qr = lane >> 2;
        const int qc = (lane & 3) * 2;
        const int mrow0 = m0 + wm * 16 + qr;
        const int mrow1 = mrow0 + 8;
        float p0 = 0.f, p1 = 0.f;
        #pragma unroll
        for (int g = 0; g < 2; g++) {
            float* acc = g ? acc1 : acc0;
            float e0 = __expf(acc[0]), e1 = __expf(acc[1]);
            float e2 = __expf(acc[2]), e3 = __expf(acc[3]);
            p0 += e0 + e1; p1 += e2 + e3;
            const int n = n0 + wn * 16 + g * 8 + qc;
            *(uint32_t*)&g_Ef[mrow0 * 512 + n] = pack_h2(e0, e1);
            *(uint32_t*)&g_Ef[mrow1 * 512 + n] = pack_h2(e2, e3);
        }
        p0 += __shfl_xor_sync(0xFFFFFFFFu, p0, 1);
        p0 += __shfl_xor_sync(0xFFFFFFFFu, p0, 2);
        p1 += __shfl_xor_sync(0xFFFFFFFFu, p1, 1);
        p1 += __shfl_xor_sync(0xFFFFFFFFu, p1, 2);
        if ((lane & 3) == 0) {
            srs[wn][wm * 16 + qr]     = p0;
            srs[wn][wm * 16 + qr + 8] = p1;
        }
    }
    __syncthreads();
    if (tid < 32) g_rs[nt * 256 + m0 + tid] = srs[0][tid] + srs[1][tid];

    // =================== GRID SYNC ===================
    grid_sync(tid, (int)gridDim.x);

    // =================== PHASE 2: y = E @ ub + rowsum + 512 ===================
    const int n0b = nt * 64;

    float* rst = (float*)(smem + RED_OFF + 24576);
    if (tid < 32) {
        float s = 512.0f;
        #pragma unroll
        for (int j = 0; j < 16; j++) s += g_rs[j * 256 + m0 + tid];
        rst[tid] = s;
    }

    // loaders: E 1 cp16/thread, u 2 cp16/thread per chunk (K=128 chunks)
    const int rowE = tid >> 4, segE = tid & 15;
    const __half* aSrc = g_Ef + (m0 + rowE) * 512 + segE * 8;
    const uint32_t aDst = sb + (uint32_t)((rowE * P + segE * 8) * 2);
    const int uIdx0 = tid * 2, uIdx1 = tid * 2 + 1;
    const int kr0 = uIdx0 >> 3, sg0 = uIdx0 & 7;
    const int kr1 = uIdx1 >> 3, sg1 = uIdx1 & 7;
    const __half* bSrc0 = g_ub + kr0 * 1024 + n0b + sg0 * 8;
    const __half* bSrc1 = g_ub + kr1 * 1024 + n0b + sg1 * 8;
    const uint32_t bDst0 = sb + (uint32_t)(ET2B + (kr0 * P + sg0 * 8) * 2);
    const uint32_t bDst1 = sb + (uint32_t)(ET2B + (kr1 * P + sg1 * 8) * 2);

    #define G2_ISSUE(c) do { \
        const uint32_t _so = (c) * STG2B; \
        cp16(aDst + _so, aSrc + (c) * 128); \
        cp16(bDst0 + _so, bSrc0 + (c) * 128 * 1024); \
        cp16(bDst1 + _so, bSrc1 + (c) * 128 * 1024); \
        CP_COMMIT(); \
    } while (0)

    const uint32_t a2Off = (uint32_t)(((wm * 16 + lrow) * P + lk) * 2);
    const int li = lane & 7, kbit = (lane >> 3) & 1, nq = lane >> 4;
    const uint32_t tOff = (uint32_t)((((kbit * 8 + li) * P) + nq * 8) * 2);

    float acc[4][4] = {};

    G2_ISSUE(0); G2_ISSUE(1); G2_ISSUE(2); G2_ISSUE(3);

    #pragma unroll
    for (int c = 0; c < 4; c++) {
        if (c == 0) CP_WAITN(3);
        else if (c == 1) CP_WAITN(2);
        else if (c == 2) CP_WAITN(1);
        else CP_WAITN(0);
        __syncthreads();
        const uint32_t st = sb + c * STG2B;                 // FIXED: + sb
        const uint32_t stU = st + ET2B;
        #pragma unroll
        for (int j = 0; j < 2; j++) {
            const int ks = wk * 2 + j;
            uint32_t a[4], bq0[4], bq1[4];
            ldsm4(a, st + a2Off + ks * 32);
            ldsm4t(bq0, stU + tOff + ks * 16 * P * 2 + (wn * 32 + 0) * 2);
            ldsm4t(bq1, stU + tOff + ks * 16 * P * 2 + (wn * 32 + 16) * 2);
            mma_f16(acc[0], a, bq0[0], bq0[1]);
            mma_f16(acc[1], a, bq0[2], bq0[3]);
            mma_f16(acc[2], a, bq1[0], bq1[1]);
            mma_f16(acc[3], a, bq1[2], bq1[3]);
        }
    }
    #undef G2_ISSUE

    // k-split reduction: sred2[12][32][16]
    float (*sred2)[32][16] = (float(*)[32][16])sredf;
    __syncthreads();
    if (wk != 0) {
        #pragma unroll
        for (int g = 0; g < 4; g++)
            #pragma unroll
            for (int i = 0; i < 4; i++)
                sred2[(wk - 1) * 4 + (wid & 3)][lane][g * 4 + i] = acc[g][i];
    }
    __syncthreads();

    if (wk == 0) {
        #pragma unroll
        for (int q = 0; q < 3; q++)
            #pragma unroll
            for (int g = 0; g < 4; g++)
                #pragma unroll
                for (int i = 0; i < 4; i++)
                    acc[g][i] += sred2[q * 4 + wid][lane][g * 4 + i];

        const int qr = lane >> 2;
        const int qc = (lane & 3) * 2;
        const int mrow0 = m0 + wm * 16 + qr;
        const int mrow1 = mrow0 + 8;
        const float r0v = rst[wm * 16 + qr];
        const float r1v = rst[wm * 16 + qr + 8];
        #pragma unroll
        for (int g = 0; g < 4; g++) {
            const int n = n0b + wn * 32 + g * 8 + qc;
            *(float2*)(Y + mrow0 * 1024 + n) = make_float2(acc[g][0] + r0v, acc[g][1] + r0v);
            *(float2*)(Y + mrow1 * 1024 + n) = make_float2(acc[g][2] + r1v, acc[g][3] + r1v);
        }
    }
}

// ============================================================
extern "C" void kernel_launch(void* const* d_in, const int* in_sizes, int n_in,
                              void* d_out, int out_size)
{
    const float* x = (const float*)d_in[0];   // 256 x 1024
    const float* W = (const float*)d_in[1];   // 512 x 1024
    const float* u = (const float*)d_in[2];   // 512 x 1024
    float* y = (float*)d_out;                 // 256 x 1024

    cudaFuncSetAttribute(fused_kernel, cudaFuncAttributeMaxDynamicSharedMemorySize, DSMEM);
    fused_kernel<<<128, 512, DSMEM>>>(x, W, u, y);
}